// round 5
// baseline (speedup 1.0000x reference)
#include <cuda_runtime.h>
#include <cstdint>

#define S_DIM 2048
#define QT 8
#define KT 128
#define NTHR 256
#define SCS 2052          // score row stride (words), mod 32 = 4
#define BFS 68            // K/V tile row stride (words), mod 32 = 4
#define OUT_O_ELEMS 4194304ull

struct __align__(16) Smem {
  float sc[QT * SCS];     // 65664 B : unnormalized p~ (tf32-rounded)
  float buf[KT * BFS];    // 34816 B : K tile, then V tile (swizzled)
  float qs[QT * BFS];     // 2176 B
  float red[8 * 8];       // per-warp row-sum partials
  float inv[8];
};                        // ~102.9 KB -> 2 CTAs/SM

__device__ __forceinline__ float tf32f(float x) {
  uint32_t u; asm("cvt.rna.tf32.f32 %0, %1;" : "=r"(u) : "f"(x));
  return __uint_as_float(u);
}
__device__ __forceinline__ void mma8(float c[4], const uint32_t a[4],
                                     uint32_t b0, uint32_t b1) {
  asm volatile("mma.sync.aligned.m16n8k8.row.col.f32.tf32.tf32.f32 "
    "{%0,%1,%2,%3}, {%4,%5,%6,%7}, {%8,%9}, {%0,%1,%2,%3};"
    : "+f"(c[0]), "+f"(c[1]), "+f"(c[2]), "+f"(c[3])
    : "r"(a[0]), "r"(a[1]), "r"(a[2]), "r"(a[3]), "r"(b0), "r"(b1));
}

__global__ void __launch_bounds__(NTHR, 2)
attn_mma_kernel(const float* __restrict__ Q, const float* __restrict__ K,
                const float* __restrict__ V, float* __restrict__ out) {
  extern __shared__ __align__(16) unsigned char smraw[];
  Smem* sm = reinterpret_cast<Smem*>(smraw);
  const int tid = threadIdx.x;
  const int w = tid >> 5, lane = tid & 31;
  const int gid = lane >> 2, tg = lane & 3;
  const int bh = blockIdx.y;
  const int qt = (int)gridDim.x - 1 - (int)blockIdx.x;   // heavy tiles first
  const int q0 = qt * QT;

  const float* Qg = Q + ((size_t)bh * S_DIM + q0) * 64;
  const float* Kg = K + (size_t)bh * S_DIM * 64;
  const float* Vg = V + (size_t)bh * S_DIM * 64;
  float* Og = out + ((size_t)bh * S_DIM + q0) * 64;
  float* Wg = out + OUT_O_ELEMS + ((size_t)bh * S_DIM + q0) * (size_t)S_DIM;

  // ---- stage Q (x 1/sqrt(64), tf32-rounded): 8 rows x 16 float4 ----
  if (tid < 128) {
    int r = tid >> 4, f = tid & 15;
    float4 v = ((const float4*)Qg)[r * 16 + f];
    float* d = &sm->qs[r * BFS + 4 * f];
    d[0] = tf32f(v.x * 0.125f); d[1] = tf32f(v.y * 0.125f);
    d[2] = tf32f(v.z * 0.125f); d[3] = tf32f(v.w * 0.125f);
  }
  __syncthreads();

  // ---- hoist Q A-fragments; rows 8..15 of the m16 atom are zero ----
  uint32_t af[8][4];
  #pragma unroll
  for (int s = 0; s < 8; ++s) {
    af[s][0] = __float_as_uint(sm->qs[gid * BFS + s * 8 + tg]);
    af[s][1] = 0u;
    af[s][2] = __float_as_uint(sm->qs[gid * BFS + s * 8 + tg + 4]);
    af[s][3] = 0u;
  }

  const int nkt = (q0 + QT + KT - 1) >> 7;
  const int n0w = w * 16;              // QK: 16 k-cols per warp
  float rs0 = 0.f;
  float oc[4] = {0.f, 0.f, 0.f, 0.f};  // PV: rows gid x cols [8w+2tg, +1]

  for (int t = 0; t < nkt; ++t) {
    const int kc = t * KT;
    __syncthreads();
    // ---- stage K tile (tf32-rounded) ----
    {
      const float4* kg = (const float4*)(Kg + (size_t)kc * 64);
      #pragma unroll
      for (int it = 0; it < 8; ++it) {
        int idx = tid + it * NTHR;
        int n = idx >> 4, f = idx & 15;
        float4 v = kg[idx];
        float* d = &sm->buf[n * BFS + 4 * f];
        d[0] = tf32f(v.x); d[1] = tf32f(v.y); d[2] = tf32f(v.z); d[3] = tf32f(v.w);
      }
    }
    __syncthreads();

    // ---- QK: 8 x 16 per warp (m16 atom half-used), K=64 ----
    float acc[2][4];
    #pragma unroll
    for (int j = 0; j < 2; ++j)
      #pragma unroll
      for (int u = 0; u < 4; ++u) acc[j][u] = 0.f;
    #pragma unroll
    for (int s = 0; s < 8; ++s) {
      const int d0 = s * 8;
      #pragma unroll
      for (int j = 0; j < 2; ++j) {
        const int ncol = n0w + j * 8 + gid;
        uint32_t b0 = __float_as_uint(sm->buf[ncol * BFS + d0 + tg]);
        uint32_t b1 = __float_as_uint(sm->buf[ncol * BFS + d0 + tg + 4]);
        mma8(acc[j], af[s], b0, b1);
      }
    }

    // ---- mask + exp + store p~ + row-sum (rows gid only) ----
    #pragma unroll
    for (int j = 0; j < 2; ++j) {
      const int cg = kc + n0w + j * 8 + 2 * tg;
      const int r0 = q0 + gid;
      float e00 = (cg     <= r0) ? tf32f(__expf(acc[j][0])) : 0.f;
      float e01 = (cg + 1 <= r0) ? tf32f(__expf(acc[j][1])) : 0.f;
      rs0 += e00 + e01;
      *(float2*)&sm->sc[gid * SCS + cg] = make_float2(e00, e01);
    }
    __syncthreads();   // buf reads done; p~ visible

    // ---- stage V tile (8-word cyclic swizzle by k&3, tf32-rounded) ----
    {
      const float4* vg = (const float4*)(Vg + (size_t)kc * 64);
      #pragma unroll
      for (int it = 0; it < 8; ++it) {
        int idx = tid + it * NTHR;
        int k = idx >> 4, f = idx & 15;
        float4 v = vg[idx];
        float* d = &sm->buf[k * BFS + ((4 * f + 8 * (k & 3)) & 63)];
        d[0] = tf32f(v.x); d[1] = tf32f(v.y); d[2] = tf32f(v.z); d[3] = tf32f(v.w);
      }
    }
    __syncthreads();

    // ---- PV: each warp owns one n8 d-strip, full k=128 contraction ----
    const int dcol = w * 8 + gid;
    #pragma unroll
    for (int ss = 0; ss < 16; ++ss) {
      const int k8 = ss * 8;
      uint32_t pa[4];
      pa[0] = __float_as_uint(sm->sc[gid * SCS + kc + k8 + tg]);
      pa[1] = 0u;
      pa[2] = __float_as_uint(sm->sc[gid * SCS + kc + k8 + tg + 4]);
      pa[3] = 0u;
      const int ka = k8 + tg, kb = k8 + tg + 4;
      uint32_t b0 = __float_as_uint(sm->buf[ka * BFS + ((dcol + 8 * tg) & 63)]);
      uint32_t b1 = __float_as_uint(sm->buf[kb * BFS + ((dcol + 8 * tg) & 63)]);
      mma8(oc, pa, b0, b1);
    }
  }

  // ---- row-sum reduce -> inv ----
  rs0 += __shfl_xor_sync(~0u, rs0, 1); rs0 += __shfl_xor_sync(~0u, rs0, 2);
  if (tg == 0) sm->red[w * 8 + gid] = rs0;
  __syncthreads();
  if (tid < 8) {
    float s = 0.f;
    #pragma unroll
    for (int i = 0; i < 8; ++i) s += sm->red[i * 8 + tid];
    sm->inv[tid] = 1.0f / s;
  }
  __syncthreads();

  // ---- W sweep: p~ * inv, then zero-fill tail (warp r -> row r) ----
  {
    const int ktend = nkt * KT;
    const int r = tid >> 5, f = tid & 31;
    const float iv = sm->inv[r];
    float4* wrow = (float4*)(Wg + (size_t)r * S_DIM);
    int c4 = f;
    for (; c4 < (ktend >> 2); c4 += 32) {
      float4 v = *(float4*)&sm->sc[r * SCS + 4 * c4];
      v.x *= iv; v.y *= iv; v.z *= iv; v.w *= iv;
      wrow[c4] = v;
    }
    const float4 z = make_float4(0.f, 0.f, 0.f, 0.f);
    for (; c4 < (S_DIM >> 2); c4 += 32) wrow[c4] = z;
  }

  // ---- O: scale by inv, write straight from registers ----
  {
    const float iv = sm->inv[gid];
    *(float2*)&Og[gid * 64 + w * 8 + 2 * tg] = make_float2(oc[0] * iv, oc[1] * iv);
  }
}

extern "C" void kernel_launch(void* const* d_in, const int* in_sizes, int n_in,
                              void* d_out, int out_size) {
  (void)in_sizes; (void)n_in; (void)out_size;
  const float* q = (const float*)d_in[0];
  const float* k = (const float*)d_in[1];
  const float* v = (const float*)d_in[2];
  float* out = (float*)d_out;

  cudaFuncSetAttribute(attn_mma_kernel,
                       cudaFuncAttributeMaxDynamicSharedMemorySize,
                       (int)sizeof(Smem));
  dim3 grid(S_DIM / QT, 32);
  attn_mma_kernel<<<grid, NTHR, sizeof(Smem)>>>(q, k, v, out);
}

// round 6
// speedup vs baseline: 1.3738x; 1.3738x over previous
#include <cuda_runtime.h>
#include <cstdint>

#define S_DIM 2048
#define QT 16
#define KT 128
#define NTHR 512
#define SCS 2052           // score row stride (words), mod 32 = 4
#define KBS 68             // K tile row stride (words)
#define OUT_O_ELEMS 4194304ull

// word offsets in dynamic smem
#define SCW 0                       // 16*2052           = 32832 w
#define KBW 32832                   // 2*128*68          = 17408 w
#define QSW (KBW + 17408)           // 16*68             = 1088 w
#define REDW (QSW + 1088)           // 16*16             = 256 w
#define INVW (REDW + 256)           // 16 w
#define SM_BYTES ((INVW + 16) * 4)  // 206464 B

__device__ __forceinline__ uint32_t smem_u32(const void* p) {
  uint32_t a;
  asm("{ .reg .u64 t; cvta.to.shared.u64 t, %1; cvt.u32.u64 %0, t; }" : "=r"(a) : "l"(p));
  return a;
}
__device__ __forceinline__ float tf32f(float x) {
  uint32_t u; asm("cvt.rna.tf32.f32 %0, %1;" : "=r"(u) : "f"(x));
  return __uint_as_float(u);
}
__device__ __forceinline__ void mma8(float c[4], const uint32_t a[4],
                                     uint32_t b0, uint32_t b1) {
  asm volatile("mma.sync.aligned.m16n8k8.row.col.f32.tf32.tf32.f32 "
    "{%0,%1,%2,%3}, {%4,%5,%6,%7}, {%8,%9}, {%0,%1,%2,%3};"
    : "+f"(c[0]), "+f"(c[1]), "+f"(c[2]), "+f"(c[3])
    : "r"(a[0]), "r"(a[1]), "r"(a[2]), "r"(a[3]), "r"(b0), "r"(b1));
}
#define CP16(dst, src) asm volatile("cp.async.ca.shared.global [%0], [%1], 16;" :: "r"(dst), "l"(src) : "memory")
#define CP_COMMIT()    asm volatile("cp.async.commit_group;" ::: "memory")
#define CP_WAIT0()     asm volatile("cp.async.wait_group 0;" ::: "memory")

__global__ void __launch_bounds__(NTHR, 1)
attn_mma_kernel(const float* __restrict__ Q, const float* __restrict__ K,
                const float* __restrict__ V, float* __restrict__ out) {
  extern __shared__ __align__(16) float smf[];
  const uint32_t sb = smem_u32(smf);
  const int tid = threadIdx.x;
  const int w = tid >> 5, lane = tid & 31;
  const int gid = lane >> 2, tg = lane & 3;
  const int bh = blockIdx.y;
  const int qt = (int)gridDim.x - 1 - (int)blockIdx.x;   // heavy tiles first
  const int q0 = qt * QT;

  const float* Qg = Q + ((size_t)bh * S_DIM + q0) * 64;
  const float* Kg = K + (size_t)bh * S_DIM * 64;
  const float* Vg = V + (size_t)bh * S_DIM * 64;
  float* Og = out + ((size_t)bh * S_DIM + q0) * 64;
  float* Wg = out + OUT_O_ELEMS + ((size_t)bh * S_DIM + q0) * (size_t)S_DIM;

  const int nkt = (q0 + QT + KT - 1) >> 7;

  // ---- stage Q (x 1/8, rna-tf32) ----
  if (tid < 256) {
    int r = tid >> 4, f = tid & 15;
    float4 v = ((const float4*)Qg)[r * 16 + f];
    float* d = &smf[QSW + r * KBS + 4 * f];
    d[0] = tf32f(v.x * 0.125f); d[1] = tf32f(v.y * 0.125f);
    d[2] = tf32f(v.z * 0.125f); d[3] = tf32f(v.w * 0.125f);
  }
  // ---- prolog: prefetch K tile 0 (raw fp32) ----
  {
    const char* kg0 = (const char*)Kg;
    #pragma unroll
    for (int it = 0; it < 4; ++it) {
      int idx = tid + it * NTHR;           // 2048 16B chunks
      int r = idx >> 4, c = idx & 15;
      CP16(sb + KBW * 4 + r * (KBS * 4) + c * 16, kg0 + r * 256 + c * 16);
    }
    CP_COMMIT();
  }
  __syncthreads();

  // ---- hoist Q A-fragments ----
  uint32_t af[8][4];
  #pragma unroll
  for (int s = 0; s < 8; ++s) {
    af[s][0] = __float_as_uint(smf[QSW + gid * KBS + s * 8 + tg]);
    af[s][1] = __float_as_uint(smf[QSW + (gid + 8) * KBS + s * 8 + tg]);
    af[s][2] = __float_as_uint(smf[QSW + gid * KBS + s * 8 + tg + 4]);
    af[s][3] = __float_as_uint(smf[QSW + (gid + 8) * KBS + s * 8 + tg + 4]);
  }

  float rs0 = 0.f, rs1 = 0.f;
  float oc[8][4];
  #pragma unroll
  for (int j = 0; j < 8; ++j)
    #pragma unroll
    for (int u = 0; u < 4; ++u) oc[j][u] = 0.f;

  const int r0 = q0 + gid, r1 = r0 + 8;

  for (int tt = 0; tt < nkt; ++tt) {
    const int kc = tt << 7;
    CP_WAIT0();
    __syncthreads();           // K(tt) visible; everyone done with kbuf[(tt-1)&1]
    if (tt + 1 < nkt) {        // prefetch K(tt+1) into the other buffer
      const char* kg1 = (const char*)(Kg + (size_t)(kc + KT) * 64);
      uint32_t dstb = sb + (KBW + ((tt + 1) & 1) * KT * KBS) * 4;
      #pragma unroll
      for (int it = 0; it < 4; ++it) {
        int idx = tid + it * NTHR;
        int r = idx >> 4, c = idx & 15;
        CP16(dstb + r * (KBS * 4) + c * 16, kg1 + r * 256 + c * 16);
      }
      CP_COMMIT();
    }
    const float* kb = &smf[KBW + (tt & 1) * KT * KBS];

    // ---- QK: warp's own n8 strip, k(d)=64 ----
    float acc[4] = {0.f, 0.f, 0.f, 0.f};
    const int ncol = w * 8 + gid;
    #pragma unroll
    for (int s = 0; s < 8; ++s) {
      uint32_t b0 = __float_as_uint(tf32f(kb[ncol * KBS + s * 8 + tg]));
      uint32_t b1 = __float_as_uint(tf32f(kb[ncol * KBS + s * 8 + tg + 4]));
      mma8(acc, af[s], b0, b1);
    }

    // ---- mask + exp + store p~ + row-sum ----
    const int cg = kc + w * 8 + 2 * tg;
    {
      float e00 = (cg     <= r0) ? tf32f(__expf(acc[0])) : 0.f;
      float e01 = (cg + 1 <= r0) ? tf32f(__expf(acc[1])) : 0.f;
      float e10 = (cg     <= r1) ? tf32f(__expf(acc[2])) : 0.f;
      float e11 = (cg + 1 <= r1) ? tf32f(__expf(acc[3])) : 0.f;
      rs0 += e00 + e01; rs1 += e10 + e11;
      *(float2*)&smf[SCW + gid * SCS + cg]       = make_float2(e00, e01);
      *(float2*)&smf[SCW + (gid + 8) * SCS + cg] = make_float2(e10, e11);
    }
    __syncwarp();   // warp-local: A-frag reads below only touch this warp's stores

    // ---- A-fragments (p~) in PV layout, conflict-free LDS ----
    uint32_t pa[4];
    const int kcb = kc + w * 8;
    pa[0] = __float_as_uint(smf[SCW + gid * SCS + kcb + tg]);
    pa[1] = __float_as_uint(smf[SCW + (gid + 8) * SCS + kcb + tg]);
    pa[2] = __float_as_uint(smf[SCW + gid * SCS + kcb + tg + 4]);
    pa[3] = __float_as_uint(smf[SCW + (gid + 8) * SCS + kcb + tg + 4]);

    // ---- PV: warp's k8 slice x all 64 d-cols, V direct from gmem ----
    const float* vr = Vg + (size_t)kcb * 64;
    #pragma unroll
    for (int j = 0; j < 8; ++j) {
      uint32_t b0 = __float_as_uint(tf32f(vr[tg * 64 + j * 8 + gid]));
      uint32_t b1 = __float_as_uint(tf32f(vr[(tg + 4) * 64 + j * 8 + gid]));
      mma8(oc[j], pa, b0, b1);
    }
  }

  // ---- row-sum reduce -> inv ----
  rs0 += __shfl_xor_sync(~0u, rs0, 1); rs0 += __shfl_xor_sync(~0u, rs0, 2);
  rs1 += __shfl_xor_sync(~0u, rs1, 1); rs1 += __shfl_xor_sync(~0u, rs1, 2);
  if (tg == 0) { smf[REDW + w * 16 + gid] = rs0; smf[REDW + w * 16 + gid + 8] = rs1; }
  __syncthreads();
  if (tid < 16) {
    float s = 0.f;
    #pragma unroll
    for (int i = 0; i < 16; ++i) s += smf[REDW + i * 16 + tid];
    smf[INVW + tid] = 1.0f / s;
  }
  __syncthreads();

  // ---- W sweep: p~ * inv, then zero-fill tail ----
  {
    const int ktend = nkt * KT;
    const int r = tid >> 5, f = tid & 31;
    const float iv = smf[INVW + r];
    float4* wrow = (float4*)(Wg + (size_t)r * S_DIM);
    int c4 = f;
    for (; c4 < (ktend >> 2); c4 += 32) {
      float4 v = *(float4*)&smf[SCW + r * SCS + 4 * c4];
      v.x *= iv; v.y *= iv; v.z *= iv; v.w *= iv;
      wrow[c4] = v;
    }
    const float4 z = make_float4(0.f, 0.f, 0.f, 0.f);
    for (; c4 < (S_DIM >> 2); c4 += 32) wrow[c4] = z;
  }
  __syncthreads();   // sc free now — reuse as O-merge scratch

  // ---- O merge: 16 per-warp partials -> O ----
  {
    float* osc = &smf[SCW + w * (16 * KBS)];
    #pragma unroll
    for (int j = 0; j < 8; ++j) {
      *(float2*)&osc[gid * KBS + j * 8 + 2 * tg]       = make_float2(oc[j][0], oc[j][1]);
      *(float2*)&osc[(gid + 8) * KBS + j * 8 + 2 * tg] = make_float2(oc[j][2], oc[j][3]);
    }
  }
  __syncthreads();
  {
    #pragma unroll
    for (int e = tid; e < 1024; e += NTHR) {
      const int r = e >> 6, d = e & 63;
      float s = 0.f;
      #pragma unroll
      for (int p = 0; p < 16; ++p) s += smf[SCW + p * (16 * KBS) + r * KBS + d];
      Og[r * 64 + d] = s * smf[INVW + r];
    }
  }
}

extern "C" void kernel_launch(void* const* d_in, const int* in_sizes, int n_in,
                              void* d_out, int out_size) {
  (void)in_sizes; (void)n_in; (void)out_size;
  const float* q = (const float*)d_in[0];
  const float* k = (const float*)d_in[1];
  const float* v = (const float*)d_in[2];
  float* out = (float*)d_out;

  cudaFuncSetAttribute(attn_mma_kernel,
                       cudaFuncAttributeMaxDynamicSharedMemorySize, SM_BYTES);
  dim3 grid(S_DIM / QT, 32);
  attn_mma_kernel<<<grid, NTHR, SM_BYTES>>>(q, k, v, out);
}